// round 3
// baseline (speedup 1.0000x reference)
#include <cuda_runtime.h>
#include <math.h>

#define SS 7
#define NCLS 20
#define ROWS_PER_BLOCK 128
#define NROW_TOTAL (8192 * 7 * 7)
#define NBLOCKS (NROW_TOTAL / ROWS_PER_BLOCK)   // 3136 exactly

// scratch accumulators (zero-initialized at module load; reset by last block):
// 0 contain_num, 1 obj_num, 2 notcontain_num, 3 noobj_num,
// 4 cls_num, 5 sum_iou, 6 acc, 7 n_obj
__device__ double g_sums[8];
__device__ unsigned int g_count;

__global__ void __launch_bounds__(ROWS_PER_BLOCK)
loss_fused_kernel(const float* __restrict__ out, const float* __restrict__ tgt,
                  float* __restrict__ outp) {
    __shared__ float s_out[ROWS_PER_BLOCK * 30];
    __shared__ float s_tgt[ROWS_PER_BLOCK * 30];

    const int t = threadIdx.x;
    const size_t base = (size_t)blockIdx.x * (ROWS_PER_BLOCK * 30);

    // Stage the block's contiguous 15360-B chunk via float4 (16B aligned)
    const float4* o4 = (const float4*)(out + base);
    const float4* t4 = (const float4*)(tgt + base);
    float4* so4 = (float4*)s_out;
    float4* st4 = (float4*)s_tgt;
    constexpr int NV4 = ROWS_PER_BLOCK * 30 / 4;  // 960
#pragma unroll
    for (int i = t; i < NV4; i += ROWS_PER_BLOCK) {
        so4[i] = o4[i];
        st4[i] = t4[i];
    }
    __syncthreads();

    const float* o = s_out + t * 30;
    const float* g = s_tgt + t * 30;

    const float m = (g[4] > 0.0f) ? 1.0f : 0.0f;

    const float inv_s = 1.0f / (float)SS;

    // target box corners
    const float tx0 = g[0] * inv_s - 0.5f * g[2];
    const float ty0 = g[1] * inv_s - 0.5f * g[3];
    const float tx1 = g[0] * inv_s + 0.5f * g[2];
    const float ty1 = g[1] * inv_s + 0.5f * g[3];
    const float at  = (tx1 - tx0) * (ty1 - ty0);

    float iou[2];
#pragma unroll
    for (int b = 0; b < 2; b++) {
        const float* pb = o + b * 5;
        const float px0 = pb[0] * inv_s - 0.5f * pb[2];
        const float py0 = pb[1] * inv_s - 0.5f * pb[3];
        const float px1 = pb[0] * inv_s + 0.5f * pb[2];
        const float py1 = pb[1] * inv_s + 0.5f * pb[3];
        const float ap  = (px1 - px0) * (py1 - py0);
        const float ulx = fmaxf(px0, tx0);
        const float uly = fmaxf(py0, ty0);
        const float lrx = fminf(px1, tx1);
        const float lry = fminf(py1, ty1);
        const float wi  = fmaxf(lrx - ulx, 0.0f);
        const float hi  = fmaxf(lry - uly, 0.0f);
        const float inter = wi * hi;
        iou[b] = inter / (ap + at - inter);
    }

    // argmax ties -> first index, so box 1 wins only on strict >
    const int resp = (iou[1] > iou[0]) ? 1 : 0;
    const float max_iou = fmaxf(iou[0], iou[1]);
    const float min_iou = fminf(iou[0], iou[1]);

    const float* rb = o + resp * 5;
    const float* nb = o + (1 - resp) * 5;

    const float dx = rb[0] - g[0];
    const float dy = rb[1] - g[1];
    const float dw = sqrtf(rb[2]) - sqrtf(g[2]);
    const float dh = sqrtf(rb[3]) - sqrtf(g[3]);
    const float contain = dx * dx + dy * dy + dw * dw + dh * dh;

    const float d_obj = rb[4] - max_iou;
    const float objl  = d_obj * d_obj;
    const float notc  = nb[4] * nb[4];

    const float dn0 = o[4] - g[4];
    const float dn1 = o[9] - g[9];
    const float noobj = dn0 * dn0 + dn1 * dn1;

    float cls = 0.0f;
    int pa = 0, ta = 0;
    float pbest = o[10], tbest = g[10];
#pragma unroll
    for (int k = 0; k < NCLS; k++) {
        const float po = o[10 + k];
        const float tg = g[10 + k];
        const float d = po - tg;
        cls += d * d;
        if (po > pbest) { pbest = po; pa = k; }
        if (tg > tbest) { tbest = tg; ta = k; }
    }
    const float accv = (m > 0.0f && pa == ta) ? 1.0f : 0.0f;

    float vals[8];
    vals[0] = m * contain;
    vals[1] = m * objl;
    vals[2] = m * notc;
    vals[3] = (1.0f - m) * noobj;
    vals[4] = m * cls;
    vals[5] = m * min_iou;
    vals[6] = accv;
    vals[7] = m;

    // warp reduce
#pragma unroll
    for (int off = 16; off > 0; off >>= 1) {
#pragma unroll
        for (int j = 0; j < 8; j++)
            vals[j] += __shfl_down_sync(0xFFFFFFFFu, vals[j], off);
    }

    __shared__ float s_red[4][8];
    const int warp = t >> 5;
    const int lane = t & 31;
    if (lane == 0) {
#pragma unroll
        for (int j = 0; j < 8; j++) s_red[warp][j] = vals[j];
    }
    __syncthreads();

    if (warp == 0 && lane < 8) {
        float s = s_red[0][lane] + s_red[1][lane] + s_red[2][lane] + s_red[3][lane];
        atomicAdd(&g_sums[lane], (double)s);
    }

    // ---- last-block finalize + reset (keeps graph replays deterministic) ----
    __shared__ bool is_last;
    if (t == 0) {
        __threadfence();
        unsigned int v = atomicAdd(&g_count, 1u);
        is_last = (v == (unsigned int)(NBLOCKS - 1));
    }
    __syncthreads();

    if (is_last && t == 0) {
        const double n_obj   = g_sums[7];
        const double n_noobj = (double)NROW_TOTAL - n_obj;

        const double contain_l  = g_sums[0] / (2.0 * n_obj);
        const double obj_loss   = g_sums[1] / n_obj;
        const double not_cont   = g_sums[2] / n_obj;
        const double noobj_loss = g_sums[3] / (2.0 * n_noobj);
        const double cls_loss   = g_sums[4] / (n_obj * (double)NCLS);

        const double loss = 5.0 * contain_l + obj_loss
                          + 0.5 * (noobj_loss + not_cont) + cls_loss;

        outp[0] = (float)loss;
        outp[1] = (float)g_sums[5];
        outp[2] = (float)g_sums[6];

        // reset for the next (graph-replayed) invocation
#pragma unroll
        for (int j = 0; j < 8; j++) g_sums[j] = 0.0;
        __threadfence();
        g_count = 0u;
    }
}

extern "C" void kernel_launch(void* const* d_in, const int* in_sizes, int n_in,
                              void* d_out, int out_size) {
    const float* out_t = (const float*)d_in[0];
    const float* tgt_t = (const float*)d_in[1];
    float* res = (float*)d_out;

    loss_fused_kernel<<<NBLOCKS, ROWS_PER_BLOCK>>>(out_t, tgt_t, res);
}

// round 4
// speedup vs baseline: 1.4075x; 1.4075x over previous
#include <cuda_runtime.h>
#include <math.h>

#define SS 7
#define NCLS 20
#define TPB 128
#define ROWS_PER_TILE 128
#define NROW_TOTAL (8192 * 7 * 7)                 // 401408
#define NTILES (NROW_TOTAL / ROWS_PER_TILE)       // 3136
#define TILES_PER_BLOCK 7
#define NBLOCKS (NTILES / TILES_PER_BLOCK)        // 448 exactly
#define TILE_F4 (ROWS_PER_TILE * 30 / 4)          // 960 float4 per array
#define TILE_F4_BOTH (2 * TILE_F4)                // 1920 float4 per tile (out+tgt)
#define SMEM_BYTES (2 * TILE_F4_BOTH * 16)        // 61440 B (double buffer)

// accumulators (zero at module load; reset by last block each invocation):
// 0: A (combined obj-side numerator), 1: B (noobj numerator),
// 2: sum_iou, 3: acc, 4: n_obj
__device__ double g_sums[5];
__device__ unsigned int g_count;

extern __shared__ float4 s_buf[];   // [2][TILE_F4_BOTH]

__device__ __forceinline__ void prefetch_tile(const float* __restrict__ outp,
                                              const float* __restrict__ tgtp,
                                              int tile, int buf, int t) {
    const float4* src_o = (const float4*)outp + (size_t)tile * TILE_F4;
    const float4* src_t = (const float4*)tgtp + (size_t)tile * TILE_F4;
    float4* dst = s_buf + buf * TILE_F4_BOTH;
#pragma unroll
    for (int j = 0; j < 15; j++) {
        const int idx = t + TPB * j;
        const float4* src = (idx < TILE_F4) ? (src_o + idx) : (src_t + (idx - TILE_F4));
        unsigned sdst = (unsigned)__cvta_generic_to_shared(dst + idx);
        asm volatile("cp.async.cg.shared.global [%0], [%1], 16;" :: "r"(sdst), "l"(src));
    }
    asm volatile("cp.async.commit_group;");
}

__global__ void __launch_bounds__(TPB)
loss_pipe_kernel(const float* __restrict__ outp_g, const float* __restrict__ tgt_g,
                 float* __restrict__ res) {
    const int t = threadIdx.x;
    const int tile0 = blockIdx.x * TILES_PER_BLOCK;

    float accA = 0.0f, accB = 0.0f, accI = 0.0f, accC = 0.0f, accM = 0.0f;

    prefetch_tile(outp_g, tgt_g, tile0, 0, t);

    for (int i = 0; i < TILES_PER_BLOCK; i++) {
        if (i + 1 < TILES_PER_BLOCK) {
            prefetch_tile(outp_g, tgt_g, tile0 + i + 1, (i + 1) & 1, t);
            asm volatile("cp.async.wait_group 1;");
        } else {
            asm volatile("cp.async.wait_group 0;");
        }
        __syncthreads();

        const float* o = (const float*)(s_buf + (i & 1) * TILE_F4_BOTH) + t * 30;
        const float* g = (const float*)(s_buf + (i & 1) * TILE_F4_BOTH + TILE_F4) + t * 30;

        const float m = (g[4] > 0.0f) ? 1.0f : 0.0f;
        const float inv_s = 1.0f / (float)SS;

        const float tx0 = g[0] * inv_s - 0.5f * g[2];
        const float ty0 = g[1] * inv_s - 0.5f * g[3];
        const float tx1 = g[0] * inv_s + 0.5f * g[2];
        const float ty1 = g[1] * inv_s + 0.5f * g[3];
        const float at  = (tx1 - tx0) * (ty1 - ty0);

        float iou[2];
#pragma unroll
        for (int b = 0; b < 2; b++) {
            const float* pb = o + b * 5;
            const float px0 = pb[0] * inv_s - 0.5f * pb[2];
            const float py0 = pb[1] * inv_s - 0.5f * pb[3];
            const float px1 = pb[0] * inv_s + 0.5f * pb[2];
            const float py1 = pb[1] * inv_s + 0.5f * pb[3];
            const float ap  = (px1 - px0) * (py1 - py0);
            const float ulx = fmaxf(px0, tx0);
            const float uly = fmaxf(py0, ty0);
            const float lrx = fminf(px1, tx1);
            const float lry = fminf(py1, ty1);
            const float wi  = fmaxf(lrx - ulx, 0.0f);
            const float hi  = fmaxf(lry - uly, 0.0f);
            const float inter = wi * hi;
            iou[b] = inter / (ap + at - inter);
        }

        // argmax ties -> first index: box 1 wins only on strict >
        const int resp = (iou[1] > iou[0]) ? 1 : 0;
        const float max_iou = fmaxf(iou[0], iou[1]);
        const float min_iou = fminf(iou[0], iou[1]);

        const float* rb = o + resp * 5;
        const float* nb = o + (1 - resp) * 5;

        const float dx = rb[0] - g[0];
        const float dy = rb[1] - g[1];
        const float dw = sqrtf(rb[2]) - sqrtf(g[2]);
        const float dh = sqrtf(rb[3]) - sqrtf(g[3]);
        const float contain = dx * dx + dy * dy + dw * dw + dh * dh;

        const float d_obj = rb[4] - max_iou;
        const float objl  = d_obj * d_obj;
        const float notc  = nb[4] * nb[4];

        const float dn0 = o[4] - g[4];
        const float dn1 = o[9] - g[9];
        const float noobj = dn0 * dn0 + dn1 * dn1;

        float cls = 0.0f;
        int pa = 0, ta = 0;
        float pbest = o[10], tbest = g[10];
#pragma unroll
        for (int k = 0; k < NCLS; k++) {
            const float po = o[10 + k];
            const float tg = g[10 + k];
            const float d = po - tg;
            cls += d * d;
            if (po > pbest) { pbest = po; pa = k; }
            if (tg > tbest) { tbest = tg; ta = k; }
        }

        // combined obj-side numerator:
        // loss = [2.5*contain + obj + 0.5*notc + cls/20]_sum / n_obj  +  0.25*B_sum/n_noobj
        accA += m * (2.5f * contain + objl + 0.5f * notc + cls * (1.0f / (float)NCLS));
        accB += (1.0f - m) * noobj;
        accI += m * min_iou;
        accC += (m > 0.0f && pa == ta) ? 1.0f : 0.0f;
        accM += m;

        __syncthreads();   // protect buffer (i&1) before its reuse at iter i+2
    }

    // ---- block reduction of 5 values ----
    float vals[5] = {accA, accB, accI, accC, accM};
#pragma unroll
    for (int off = 16; off > 0; off >>= 1) {
#pragma unroll
        for (int j = 0; j < 5; j++)
            vals[j] += __shfl_down_sync(0xFFFFFFFFu, vals[j], off);
    }

    __shared__ float s_red[4][5];
    const int warp = t >> 5;
    const int lane = t & 31;
    if (lane == 0) {
#pragma unroll
        for (int j = 0; j < 5; j++) s_red[warp][j] = vals[j];
    }
    __syncthreads();

    if (warp == 0 && lane < 5) {
        float s = s_red[0][lane] + s_red[1][lane] + s_red[2][lane] + s_red[3][lane];
        atomicAdd(&g_sums[lane], (double)s);
    }

    // ---- last-block finalize + reset ----
    __shared__ bool is_last;
    if (t == 0) {
        __threadfence();
        unsigned int v = atomicAdd(&g_count, 1u);
        is_last = (v == (unsigned int)(NBLOCKS - 1));
    }
    __syncthreads();

    if (is_last && t == 0) {
        double sA = atomicAdd(&g_sums[0], 0.0);
        double sB = atomicAdd(&g_sums[1], 0.0);
        double sI = atomicAdd(&g_sums[2], 0.0);
        double sC = atomicAdd(&g_sums[3], 0.0);
        double sM = atomicAdd(&g_sums[4], 0.0);

        const double n_obj   = sM;
        const double n_noobj = (double)NROW_TOTAL - n_obj;

        const double loss = sA / n_obj + 0.25 * sB / n_noobj;

        res[0] = (float)loss;
        res[1] = (float)sI;
        res[2] = (float)sC;

        // reset for next graph replay
#pragma unroll
        for (int j = 0; j < 5; j++) g_sums[j] = 0.0;
        __threadfence();
        g_count = 0u;
    }
}

extern "C" void kernel_launch(void* const* d_in, const int* in_sizes, int n_in,
                              void* d_out, int out_size) {
    const float* out_t = (const float*)d_in[0];
    const float* tgt_t = (const float*)d_in[1];
    float* res = (float*)d_out;

    // persists per-context; the pre-capture correctness call sets it for good.
    cudaFuncSetAttribute(loss_pipe_kernel,
                         cudaFuncAttributeMaxDynamicSharedMemorySize, SMEM_BYTES);

    loss_pipe_kernel<<<NBLOCKS, TPB, SMEM_BYTES>>>(out_t, tgt_t, res);
}